// round 17
// baseline (speedup 1.0000x reference)
#include <cuda_runtime.h>
#include <cuda_bf16.h>
#include <cuda_fp16.h>
#include <cstdint>

#define NTOK 6272
#define CDIM 1024
#define HEADS 16
#define HD 64
#define SFR 32
#define PTOK 196
#define MKV 1960
#define KT 32
#define MKPAD 1984
#define NSPL 2
#define NT_S 31
#define KVSPL (NT_S * KT)

#define KDIM 1024
#define NQKV 3072

// Scratch (no allocations anywhere)
__device__ __half g_a16[(size_t)NTOK * KDIM];
__device__ __half g_wq16[(size_t)NQKV * KDIM];
__device__ __half g_wp16[(size_t)1024 * KDIM];
__device__ __half g_q16[(size_t)HEADS * NTOK * HD];
__device__ __half g_k16[(size_t)HEADS * NTOK * HD];
__device__ __half g_v16[(size_t)HEADS * NTOK * HD];
__device__ int   g_gidx2[SFR * MKPAD];
__device__ float g_bias2[SFR * MKPAD];
__device__ int   g_nreal[SFR];
__device__ float g_pacc[(size_t)NSPL * SFR * HEADS * PTOK * HD];
__device__ float g_pl[NSPL * SFR * HEADS * PTOK];

// ---------------------------------------------------------------------------
// helpers
// ---------------------------------------------------------------------------
__device__ __forceinline__ uint32_t smem_u32(const void* p) {
    uint32_t a;
    asm("{ .reg .u64 t; cvta.to.shared.u64 t, %1; cvt.u32.u64 %0, t; }"
        : "=r"(a) : "l"(p));
    return a;
}
__device__ __forceinline__ void ldsm4(uint32_t addr, uint32_t& r0, uint32_t& r1,
                                      uint32_t& r2, uint32_t& r3) {
    asm volatile("ldmatrix.sync.aligned.m8n8.x4.shared.b16 {%0,%1,%2,%3}, [%4];"
                 : "=r"(r0), "=r"(r1), "=r"(r2), "=r"(r3) : "r"(addr));
}
__device__ __forceinline__ void ldsm4t(uint32_t addr, uint32_t& r0, uint32_t& r1,
                                       uint32_t& r2, uint32_t& r3) {
    asm volatile("ldmatrix.sync.aligned.m8n8.x4.trans.shared.b16 {%0,%1,%2,%3}, [%4];"
                 : "=r"(r0), "=r"(r1), "=r"(r2), "=r"(r3) : "r"(addr));
}
__device__ __forceinline__ void mma_f16(float& d0, float& d1, float& d2, float& d3,
                                        uint32_t a0, uint32_t a1, uint32_t a2, uint32_t a3,
                                        uint32_t b0, uint32_t b1) {
    asm volatile(
        "mma.sync.aligned.m16n8k16.row.col.f32.f16.f16.f32 "
        "{%0,%1,%2,%3}, {%4,%5,%6,%7}, {%8,%9}, {%0,%1,%2,%3};"
        : "+f"(d0), "+f"(d1), "+f"(d2), "+f"(d3)
        : "r"(a0), "r"(a1), "r"(a2), "r"(a3), "r"(b0), "r"(b1));
}
__device__ __forceinline__ uint32_t pack_h16(float a, float b) {
    __half2 t = __floats2half2_rn(a, b);
    return *(uint32_t*)&t;
}
__device__ __forceinline__ void cpa16(uint32_t dst, const void* src) {
    asm volatile("cp.async.cg.shared.global [%0], [%1], 16;"
                 :: "r"(dst), "l"(src) : "memory");
}
__device__ __forceinline__ void cpa_commit() {
    asm volatile("cp.async.commit_group;" ::: "memory");
}
__device__ __forceinline__ void cpa_wait1() {
    asm volatile("cp.async.wait_group 1;" ::: "memory");
}

// ---------------------------------------------------------------------------
// Convert fp32 -> fp16 plane into g_a16
// ---------------------------------------------------------------------------
__global__ void __launch_bounds__(256)
split_kernel(const float* __restrict__ src, int n4)
{
    int i = blockIdx.x * blockDim.x + threadIdx.x;
    if (i >= n4) return;
    float4 a = ((const float4*)src)[i];
    uint2 w;
    w.x = pack_h16(a.x, a.y);
    w.y = pack_h16(a.z, a.w);
    *(uint2*)&g_a16[(size_t)i * 4] = w;
}

// ---------------------------------------------------------------------------
// Pad/clamp gather indices and fold the static-max shift into the bias.
// ---------------------------------------------------------------------------
__global__ void __launch_bounds__(256)
pad_kernel(const int* __restrict__ gidx, const float* __restrict__ abias)
{
    int i = blockIdx.x * blockDim.x + threadIdx.x;
    if (i >= SFR * MKPAD) return;
    int s = i / MKPAD, j = i - s * MKPAD;
    int jj = (j < MKV) ? j : 0;
    g_gidx2[i] = gidx[s * MKV + jj];
    g_bias2[i] = (j < MKV) ? (abias[s * MKV + j] - 10.f) : -1e9f;
}

// ---------------------------------------------------------------------------
// Count real (non-padded) keys per frame: bias > -1e8. One block per frame.
// ---------------------------------------------------------------------------
__global__ void __launch_bounds__(256)
count_kernel(const float* __restrict__ abias)
{
    __shared__ int red[8];
    int s = blockIdx.x;
    int tid = threadIdx.x;
    int cnt = 0;
    for (int j = tid; j < MKV; j += 256)
        cnt += (abias[s * MKV + j] > -1e8f) ? 1 : 0;
#pragma unroll
    for (int o = 16; o; o >>= 1) cnt += __shfl_xor_sync(0xffffffffu, cnt, o);
    if ((tid & 31) == 0) red[tid >> 5] = cnt;
    __syncthreads();
    if (tid == 0) {
        int t = 0;
#pragma unroll
        for (int w = 0; w < 8; w++) t += red[w];
        g_nreal[s] = t;
    }
}

// ---------------------------------------------------------------------------
// Transpose + convert: W [1024][N] fp32 -> fp16 [N][1024]
// ---------------------------------------------------------------------------
template <int WHICH>
__global__ void __launch_bounds__(256)
wsplit_kernel(const float* __restrict__ W, int N)
{
    __half* dst = (WHICH == 0) ? g_wq16 : g_wp16;
    __shared__ float t[32][33];
    int n0 = blockIdx.x * 32, k0 = blockIdx.y * 32;
    int tx = threadIdx.x & 31, ty = threadIdx.x >> 5;
#pragma unroll
    for (int r = 0; r < 4; r++)
        t[ty + r * 8][tx] = W[(size_t)(k0 + ty + r * 8) * N + n0 + tx];
    __syncthreads();
#pragma unroll
    for (int r = 0; r < 4; r++) {
        int n = ty + r * 8;
        dst[(size_t)(n0 + n) * KDIM + k0 + tx] = __float2half_rn(t[tx][n]);
    }
}

// ---------------------------------------------------------------------------
// fp16 HMMA GEMM v2: k-chunk 32, NSTAGE 3, 256 threads, 64x32 warp tiles,
// 2 CTAs/SM. 32 barrier rounds instead of 64.
// MODE 0: fused LayerNorm + fp16 epilogue -> g_{q,k,v}16.
// MODE 1: row-major C(+bias) -> Cout.
// ---------------------------------------------------------------------------
#define RSTR 40                        // 32 elems + 8 pad = 80B rows (conflict-free)
#define CH_K 32
#define TILE_E (128 * RSTR)            // 5120 halves
#define STAGE_E (2 * TILE_E)           // A + B
#define STAGE_B (STAGE_E * 2)          // 20480 bytes
#define NSTAGE 3
#define PIPE_SMEM (NSTAGE * STAGE_B)   // 61440 bytes
#define LN_SS 130
#define GEMM_SMEM0 (128 * LN_SS * 4)   // 66560 (max of LN tile, pipe)
#define GEMM_SMEM1 PIPE_SMEM
#define OFF_A 0
#define OFF_B TILE_E

template <int MODE>
__global__ void __launch_bounds__(256, 2)
hmma_gemm_kernel(const float* __restrict__ bias, float* __restrict__ Cout, int Nc,
                 const float* __restrict__ qg, const float* __restrict__ qb,
                 const float* __restrict__ kg, const float* __restrict__ kb)
{
    extern __shared__ __half smh0[];
    const uint32_t su = smem_u32(smh0);

    const __half* Bsrc = (MODE == 0) ? g_wq16 : g_wp16;

    const int tid = threadIdx.x;
    const int wid = tid >> 5;
    const int lane = tid & 31;
    const int wm = wid & 1;
    const int wn = wid >> 1;
    const int bm = blockIdx.y * 128;
    const int bn = blockIdx.x * 128;

    const int grow = tid >> 1;
    const int ghalf = tid & 1;
    const __half* pA = g_a16 + (size_t)(bm + grow) * KDIM + ghalf * 16;
    const __half* pB = Bsrc + (size_t)(bn + grow) * KDIM + ghalf * 16;
    const uint32_t sstore = (uint32_t)(grow * RSTR + ghalf * 16) * 2;   // bytes

    const uint32_t aAddr = (uint32_t)((wm * 64 + (lane & 15)) * RSTR + (lane >> 4) * 8) * 2;
    const uint32_t bAddr = (uint32_t)((wn * 32 + (lane & 7) + ((lane >> 4) & 1) * 8) * RSTR
                                      + ((lane >> 3) & 1) * 8) * 2;

    float acc[4][4][4];
#pragma unroll
    for (int mf = 0; mf < 4; mf++)
#pragma unroll
        for (int nf = 0; nf < 4; nf++)
#pragma unroll
            for (int e = 0; e < 4; e++) acc[mf][nf][e] = 0.f;

    const int NCHUNK = KDIM / CH_K;    // 32

    auto issue_chunk = [&](int c1, int slot) {
        uint32_t sb = su + (uint32_t)slot * STAGE_B + sstore;
        int ko = c1 * CH_K;
        cpa16(sb + OFF_A * 2,      pA + ko);
        cpa16(sb + OFF_A * 2 + 16, pA + ko + 8);
        cpa16(sb + OFF_B * 2,      pB + ko);
        cpa16(sb + OFF_B * 2 + 16, pB + ko + 8);
    };

    issue_chunk(0, 0);
    cpa_commit();
    issue_chunk(1, 1);
    cpa_commit();

    for (int c = 0; c < NCHUNK; c++) {
        cpa_wait1();
        __syncthreads();

        if (c + 2 < NCHUNK) issue_chunk(c + 2, (c + 2) % NSTAGE);
        cpa_commit();

        const uint32_t sb = su + (uint32_t)(c % NSTAGE) * STAGE_B;
#pragma unroll
        for (int kf = 0; kf < 2; kf++) {
            const uint32_t kfo = kf * 32;     // 16 elems
            uint32_t bh[8];
            ldsm4(sb + OFF_B * 2 + bAddr + kfo, bh[0], bh[1], bh[2], bh[3]);
            ldsm4(sb + OFF_B * 2 + bAddr + kfo + 16 * RSTR * 2, bh[4], bh[5], bh[6], bh[7]);
#pragma unroll
            for (int mf = 0; mf < 4; mf++) {
                uint32_t a0, a1, a2, a3;
                ldsm4(sb + OFF_A * 2 + aAddr + kfo + mf * 16 * RSTR * 2, a0, a1, a2, a3);
#pragma unroll
                for (int nf = 0; nf < 4; nf++)
                    mma_f16(acc[mf][nf][0], acc[mf][nf][1], acc[mf][nf][2], acc[mf][nf][3],
                            a0, a1, a2, a3, bh[nf * 2], bh[nf * 2 + 1]);
            }
        }
        __syncthreads();
    }

    if (MODE == 1) {
#pragma unroll
        for (int mf = 0; mf < 4; mf++) {
#pragma unroll
            for (int nf = 0; nf < 4; nf++) {
                int m0 = bm + wm * 64 + mf * 16 + (lane >> 2);
                int col = bn + wn * 32 + nf * 8 + (lane & 3) * 2;
                float2 bb = *(const float2*)&bias[col];
                float2 v0, v1;
                v0.x = acc[mf][nf][0] + bb.x;
                v0.y = acc[mf][nf][1] + bb.y;
                v1.x = acc[mf][nf][2] + bb.x;
                v1.y = acc[mf][nf][3] + bb.y;
                *(float2*)&Cout[(size_t)m0 * Nc + col] = v0;
                *(float2*)&Cout[(size_t)(m0 + 8) * Nc + col] = v1;
            }
        }
    } else {
        // ---- fused LayerNorm + fp16 epilogue ----
        float* S = (float*)smh0;
#pragma unroll
        for (int mf = 0; mf < 4; mf++) {
#pragma unroll
            for (int nf = 0; nf < 4; nf++) {
                int ml = wm * 64 + mf * 16 + (lane >> 2);
                int cl = wn * 32 + nf * 8 + (lane & 3) * 2;
                float2 bb = *(const float2*)&bias[bn + cl];
                float2 v0, v1;
                v0.x = acc[mf][nf][0] + bb.x;
                v0.y = acc[mf][nf][1] + bb.y;
                v1.x = acc[mf][nf][2] + bb.x;
                v1.y = acc[mf][nf][3] + bb.y;
                *(float2*)&S[ml * LN_SS + cl] = v0;
                *(float2*)&S[(ml + 8) * LN_SS + cl] = v1;
            }
        }
        __syncthreads();

        const int row = tid & 127;
        const int hb = tid >> 7;
        const int gc = bn + hb * 64;
        const int part = gc >> 10;             // 0=q 1=k 2=v
        const int hh = (gc >> 6) & (HEADS - 1);
        const int m = bm + row;
        const float* Sr = &S[row * LN_SS + hb * 64];

        float sum = 0.f, sq = 0.f;
#pragma unroll
        for (int j = 0; j < 32; j++) {
            float2 t = *(const float2*)&Sr[j * 2];
            sum += t.x + t.y;
            sq += t.x * t.x + t.y * t.y;
        }
        float mu = 0.f, rstd = 1.f;
        const float* gp = (part == 0) ? qg : kg;
        const float* bp = (part == 0) ? qb : kb;
        if (part < 2) {
            mu = sum * (1.f / 64.f);
            float var = sq * (1.f / 64.f) - mu * mu;
            rstd = rsqrtf(var + 1e-6f);
        }
        __half* dst = (part == 0) ? g_q16 : (part == 1) ? g_k16 : g_v16;
        size_t obase = ((size_t)hh * NTOK + m) * HD;

#pragma unroll
        for (int jj = 0; jj < 8; jj++) {
            float v[8];
#pragma unroll
            for (int k = 0; k < 4; k++) {
                float2 t = *(const float2*)&Sr[jj * 8 + k * 2];
                v[k * 2] = t.x;
                v[k * 2 + 1] = t.y;
            }
            if (part < 2) {
#pragma unroll
                for (int k = 0; k < 8; k++)
                    v[k] = (v[k] - mu) * rstd * gp[jj * 8 + k] + bp[jj * 8 + k];
            }
            uint32_t w[4];
#pragma unroll
            for (int k = 0; k < 4; k++)
                w[k] = pack_h16(v[2 * k], v[2 * k + 1]);
            *(uint4*)&dst[obase + jj * 8] = *(uint4*)w;
        }
    }
}

// ---------------------------------------------------------------------------
// fp16 HMMA flash attention (attn10, R16-exact WIN version).
// ---------------------------------------------------------------------------
#define AST 72
#define KARR (KT * AST)
#define BIAS_OFF (2 * KARR)
#define AT_SMEM_BYTES (BIAS_OFF * 2 + KT * 4 + 16)

__global__ void __launch_bounds__(224, 2)
attn10_kernel()
{
    extern __shared__ __half smh[];
    __half* Tile = smh;
    float* Bs = (float*)(smh + BIAS_OFF);
    const uint32_t su = smem_u32(smh);

    const int s = blockIdx.x, h = blockIdx.y, split = blockIdx.z;
    const int tid = threadIdx.x, wid = tid >> 5, lane = tid & 31;
    const int m0 = wid * 32;

    int keys_here = g_nreal[s] - split * KVSPL;
    keys_here = keys_here < 0 ? 0 : (keys_here > KVSPL ? KVSPL : keys_here);
    const int nt = (keys_here + KT - 1) / KT;

    const __half* q16 = g_q16 + ((size_t)h * NTOK + (size_t)s * PTOK) * HD;
    const __half* k16 = g_k16 + (size_t)h * NTOK * HD;
    const __half* v16 = g_v16 + (size_t)h * NTOK * HD;

    float o[2][8][4];
    float lsum[2][2];
#pragma unroll
    for (int mf = 0; mf < 2; mf++) {
        lsum[mf][0] = 0.f; lsum[mf][1] = 0.f;
#pragma unroll
        for (int nf = 0; nf < 8; nf++)
#pragma unroll
            for (int e = 0; e < 4; e++) o[mf][nf][e] = 0.f;
    }

    if (nt > 0) {
        uint32_t qf[2][4][4];
        {
            int r = lane >> 2, c2 = (lane & 3) * 2;
#pragma unroll
            for (int mf = 0; mf < 2; mf++) {
                int r0 = m0 + mf * 16 + r;
                int r1 = r0 + 8;
                if (r0 > PTOK - 1) r0 = PTOK - 1;
                if (r1 > PTOK - 1) r1 = PTOK - 1;
#pragma unroll
                for (int kf = 0; kf < 4; kf++) {
                    int c0 = kf * 16 + c2;
                    qf[mf][kf][0] = *(const uint32_t*)(q16 + (size_t)r0 * HD + c0);
                    qf[mf][kf][1] = *(const uint32_t*)(q16 + (size_t)r1 * HD + c0);
                    qf[mf][kf][2] = *(const uint32_t*)(q16 + (size_t)r0 * HD + c0 + 8);
                    qf[mf][kf][3] = *(const uint32_t*)(q16 + (size_t)r1 * HD + c0 + 8);
                }
            }
        }

        const int pbase = s * MKPAD + split * KVSPL;

        const uint32_t kaddr = su + 2 * (
            ((lane & 7) + ((lane >> 4) & 1) * 8) * AST + ((lane >> 3) & 1) * 8);
        const uint32_t vaddr = su + 2 * (KARR
            + ((lane & 7) + ((lane >> 3) & 1) * 8) * AST + ((lane >> 4) & 1) * 8);

        uint4 pf[3];
        float pbias = 0.f;
#pragma unroll
        for (int it = 0; it < 3; it++) {
            int slot = tid + it * 224;
            if (slot < 512) {
                int a = slot >> 8, r = (slot >> 3) & 31, seg = slot & 7;
                int tok = g_gidx2[pbase + r];
                const __half* bp = (a == 0) ? k16 : v16;
                pf[it] = *(const uint4*)(bp + (size_t)tok * HD + seg * 8);
            }
        }
        if (tid < KT) pbias = g_bias2[pbase + tid];

        for (int t = 0; t < nt; t++) {
            __syncthreads();
#pragma unroll
            for (int it = 0; it < 3; it++) {
                int slot = tid + it * 224;
                if (slot < 512) {
                    int a = slot >> 8, r = (slot >> 3) & 31, seg = slot & 7;
                    *(uint4*)&Tile[a * KARR + r * AST + seg * 8] = pf[it];
                }
            }
            if (tid < KT) Bs[tid] = pbias;
            __syncthreads();

            if (t + 1 < nt) {
                int ib = pbase + (t + 1) * KT;
#pragma unroll
                for (int it = 0; it < 3; it++) {
                    int slot = tid + it * 224;
                    if (slot < 512) {
                        int a = slot >> 8, r = (slot >> 3) & 31, seg = slot & 7;
                        int tok = g_gidx2[ib + r];
                        const __half* bp = (a == 0) ? k16 : v16;
                        pf[it] = *(const uint4*)(bp + (size_t)tok * HD + seg * 8);
                    }
                }
                if (tid < KT) pbias = g_bias2[ib + tid];
            }

            float sc[2][4][4];
#pragma unroll
            for (int mf = 0; mf < 2; mf++)
#pragma unroll
                for (int nf = 0; nf < 4; nf++)
#pragma unroll
                    for (int e = 0; e < 4; e++) sc[mf][nf][e] = 0.f;

#pragma unroll
            for (int kf = 0; kf < 4; kf++) {
                uint32_t bh0[4], bh1[4];
                ldsm4(kaddr + kf * 32, bh0[0], bh0[1], bh0[2], bh0[3]);
                ldsm4(kaddr + kf * 32 + 16 * AST * 2, bh1[0], bh1[1], bh1[2], bh1[3]);
#pragma unroll
                for (int mf = 0; mf < 2; mf++) {
                    uint32_t q0 = qf[mf][kf][0], q1 = qf[mf][kf][1];
                    uint32_t q2 = qf[mf][kf][2], q3 = qf[mf][kf][3];
                    mma_f16(sc[mf][0][0], sc[mf][0][1], sc[mf][0][2], sc[mf][0][3],
                            q0, q1, q2, q3, bh0[0], bh0[1]);
                    mma_f16(sc[mf][1][0], sc[mf][1][1], sc[mf][1][2], sc[mf][1][3],
                            q0, q1, q2, q3, bh0[2], bh0[3]);
                    mma_f16(sc[mf][2][0], sc[mf][2][1], sc[mf][2][2], sc[mf][2][3],
                            q0, q1, q2, q3, bh1[0], bh1[1]);
                    mma_f16(sc[mf][3][0], sc[mf][3][1], sc[mf][3][2], sc[mf][3][3],
                            q0, q1, q2, q3, bh1[2], bh1[3]);
                }
            }

            uint32_t phi[2][2][4];
#pragma unroll
            for (int mf = 0; mf < 2; mf++) {
#pragma unroll
                for (int nf = 0; nf < 4; nf++) {
                    float2 bb = *(const float2*)&Bs[nf * 8 + (lane & 3) * 2];
                    float p0 = __expf(fmaf(sc[mf][nf][0], 0.125f, bb.x));
                    float p1 = __expf(fmaf(sc[mf][nf][1], 0.125f, bb.y));
                    float p2 = __expf(fmaf(sc[mf][nf][2], 0.125f, bb.x));
                    float p3 = __expf(fmaf(sc[mf][nf][3], 0.125f, bb.y));
                    lsum[mf][0] += p0 + p1;
                    lsum[mf][1] += p2 + p3;
                    int kf2 = nf >> 1, hf = (nf & 1) * 2;
                    phi[mf][kf2][hf] = pack_h16(p0, p1);
                    phi[mf][kf2][hf + 1] = pack_h16(p2, p3);
                }
            }

#pragma unroll
            for (int kf = 0; kf < 2; kf++) {
                uint32_t vhf[16];
#pragma unroll
                for (int db = 0; db < 4; db++) {
                    ldsm4t(vaddr + kf * (16 * AST * 2) + db * 32,
                           vhf[db * 4], vhf[db * 4 + 1], vhf[db * 4 + 2], vhf[db * 4 + 3]);
                }
#pragma unroll
                for (int mf = 0; mf < 2; mf++) {
#pragma unroll
                    for (int nfd = 0; nfd < 8; nfd++) {
                        int vi = (nfd >> 1) * 4 + (nfd & 1) * 2;
                        mma_f16(o[mf][nfd][0], o[mf][nfd][1], o[mf][nfd][2], o[mf][nfd][3],
                                phi[mf][kf][0], phi[mf][kf][1], phi[mf][kf][2], phi[mf][kf][3],
                                vhf[vi], vhf[vi + 1]);
                    }
                }
            }
        }

#pragma unroll
        for (int mf = 0; mf < 2; mf++) {
#pragma unroll
            for (int j = 0; j < 2; j++) {
                float v = lsum[mf][j];
                v += __shfl_xor_sync(0xffffffffu, v, 1);
                v += __shfl_xor_sync(0xffffffffu, v, 2);
                lsum[mf][j] = v;
            }
        }
    }

    {
        int r = lane >> 2, c2 = (lane & 3) * 2;
        const size_t rrbase = ((size_t)(split * SFR + s) * HEADS + h) * PTOK;
#pragma unroll
        for (int mf = 0; mf < 2; mf++) {
            int rowq0 = m0 + mf * 16 + r;
            int rowq1 = rowq0 + 8;
            if (rowq0 < PTOK) {
                float* dst = g_pacc + (rrbase + rowq0) * HD + c2;
#pragma unroll
                for (int nfd = 0; nfd < 8; nfd++) {
                    float2 v; v.x = o[mf][nfd][0]; v.y = o[mf][nfd][1];
                    *(float2*)(dst + nfd * 8) = v;
                }
                if ((lane & 3) == 0) g_pl[rrbase + rowq0] = lsum[mf][0];
            }
            if (rowq1 < PTOK) {
                float* dst = g_pacc + (rrbase + rowq1) * HD + c2;
#pragma unroll
                for (int nfd = 0; nfd < 8; nfd++) {
                    float2 v; v.x = o[mf][nfd][2]; v.y = o[mf][nfd][3];
                    *(float2*)(dst + nfd * 8) = v;
                }
                if ((lane & 3) == 0) g_pl[rrbase + rowq1] = lsum[mf][1];
            }
        }
    }
}

// ---------------------------------------------------------------------------
// Combine split partials: (n0+n1)/(l0+l1) -> fp16 token-major plane g_a16.
// ---------------------------------------------------------------------------
__global__ void __launch_bounds__(256)
combine_kernel()
{
    int idx = blockIdx.x * blockDim.x + threadIdx.x;
    const int total = SFR * HEADS * PTOK * (HD / 4);
    if (idx >= total) return;
    int c4 = idx & 15;
    int shp = idx >> 4;
    size_t row0 = shp;
    size_t row1 = (size_t)SFR * HEADS * PTOK + shp;
    float4 a = ((const float4*)(g_pacc + row0 * HD))[c4];
    float4 b = ((const float4*)(g_pacc + row1 * HD))[c4];
    float inv = 1.f / (g_pl[row0] + g_pl[row1]);
    float f0 = (a.x + b.x) * inv;
    float f1 = (a.y + b.y) * inv;
    float f2 = (a.z + b.z) * inv;
    float f3 = (a.w + b.w) * inv;
    int p = shp % PTOK;
    int sh = shp / PTOK;
    int hh = sh % HEADS;
    int ss = sh / HEADS;
    size_t base = (size_t)(ss * PTOK + p) * CDIM + hh * HD + c4 * 4;
    uint2 w;
    w.x = pack_h16(f0, f1);
    w.y = pack_h16(f2, f3);
    *(uint2*)&g_a16[base] = w;
}

// ---------------------------------------------------------------------------
extern "C" void kernel_launch(void* const* d_in, const int* in_sizes, int n_in,
                              void* d_out, int out_size)
{
    const float* x     = (const float*)d_in[0];
    const float* Wqkv  = (const float*)d_in[1];
    const float* bqkv  = (const float*)d_in[2];
    const float* qg    = (const float*)d_in[3];
    const float* qb    = (const float*)d_in[4];
    const float* kg    = (const float*)d_in[5];
    const float* kb    = (const float*)d_in[6];
    const float* Wproj = (const float*)d_in[7];
    const float* bproj = (const float*)d_in[8];
    const int*   gidx  = (const int*)d_in[9];
    const float* abias = (const float*)d_in[10];
    float* out = (float*)d_out;

    static int attr_set = 0;
    if (!attr_set) {
        cudaFuncSetAttribute(hmma_gemm_kernel<0>,
                             cudaFuncAttributeMaxDynamicSharedMemorySize, GEMM_SMEM0);
        cudaFuncSetAttribute(hmma_gemm_kernel<1>,
                             cudaFuncAttributeMaxDynamicSharedMemorySize, GEMM_SMEM1);
        cudaFuncSetAttribute(attn10_kernel,
                             cudaFuncAttributeMaxDynamicSharedMemorySize, AT_SMEM_BYTES);
        attr_set = 1;
    }

    const int n4 = NTOK * KDIM / 4;

    // 0) prep
    split_kernel<<<n4 / 256, 256>>>(x, n4);
    pad_kernel<<<(SFR * MKPAD + 255) / 256, 256>>>(gidx, abias);
    count_kernel<<<SFR, 256>>>(abias);
    wsplit_kernel<0><<<dim3(NQKV / 32, KDIM / 32), 256>>>(Wqkv, NQKV);
    wsplit_kernel<1><<<dim3(1024 / 32, KDIM / 32), 256>>>(Wproj, 1024);

    // 1) QKV GEMM (fp16, k32) with FUSED LayerNorm + fp16 epilogue
    hmma_gemm_kernel<0><<<dim3(NQKV / 128, NTOK / 128), 256, GEMM_SMEM0>>>(
        bqkv, nullptr, NQKV, qg, qb, kg, kb);

    // 2) fp16 flash attention, KV-split x2, live-tile skipping
    attn10_kernel<<<dim3(SFR, HEADS, NSPL), 224, AT_SMEM_BYTES>>>();

    // 2b) combine partials -> g_a16
    {
        const int total = SFR * HEADS * PTOK * (HD / 4);
        combine_kernel<<<(total + 255) / 256, 256>>>();
    }

    // 3) proj GEMM (fp16, k32) -> d_out
    hmma_gemm_kernel<1><<<dim3(1024 / 128, NTOK / 128), 256, GEMM_SMEM1>>>(
        bproj, out, 1024, nullptr, nullptr, nullptr, nullptr);
}